// round 9
// baseline (speedup 1.0000x reference)
#include <cuda_runtime.h>
#include <cuda_fp16.h>
#include <mma.h>

using namespace nvcuda;

#define NN 100000
#define NE 1000000
#define DD 64
#define NRELTAB 401
#define BB 8

#define BM 128
#define GEMM_THREADS 256
#define NGEMM_BLOCKS ((NN + BM - 1) / BM)        // 782 (last block row-guarded)
#define NPROJ_ROWS (2 * NRELTAB + BB)            // 810
#define NPROJ_BLOCKS ((NPROJ_ROWS + 3) / 4)      // 203
#define PRE_SMEM 65536                           // epilogue: 8 warps * 16*128 fp32

#define EDGE_ITERS 4
#define EDGE_BLOCKS (NE / (16 * EDGE_ITERS))     // 15625 blocks * 16 groups * 4 edges

// Scratch (static device globals — no runtime allocation).
// g_h16: per node, 128 halves: for l in 0..15: hsp[4l..4l+3] then hp2[4l..4l+3]
//   (hsp = hidden@Ws^T, hp2 = hidden@Wh^T) -> one LDG.128 per lane in edge kernel
__device__ __align__(256) __half g_h16[NN * 2 * DD];
// g_trrp: per relation, 128 halves: for l: tr[4l..4l+3], rp2[4l..4l+3]
__device__ __align__(256) __half g_trrp[NRELTAB * 2 * DD];
__device__ __align__(256) __half g_tqr16[BB * DD];   // rel_emb[q_rel]@Wqr^T + bias

// ---------------------------------------------------------------------------
// Single fused pre-kernel.
//  blocks [0, NGEMM_BLOCKS): zero d_out slice; load hidden fp32 tile ->
//    fp16 smem A [128][64]; build W16 smem [64][128] (cols: Ws^T | Wh^T);
//    wmma 16x16x16 f16->f32 entirely from smem; epilogue stages C per-warp
//    in (reused) smem and writes interleaved fp16 g_h16 rows (uint4/lane).
//  blocks [NGEMM_BLOCKS, +NPROJ_BLOCKS): fp32 relation projections (4 rows/blk).
// ---------------------------------------------------------------------------
__global__ __launch_bounds__(GEMM_THREADS)
void fused_pre_kernel(const float* __restrict__ hidden,
                      const float* __restrict__ Ws,
                      const float* __restrict__ Wh,
                      const float* __restrict__ emb,
                      const float* __restrict__ Wr,
                      const float* __restrict__ Wqr,
                      const float* __restrict__ bias,
                      const int* __restrict__ qrel,
                      float* __restrict__ out) {
    extern __shared__ float sm[];
    int t = threadIdx.x;

    if (blockIdx.x < NGEMM_BLOCKS) {
        // zero the output buffer (edge kernel REDs into it)
        {
            int i = blockIdx.x * GEMM_THREADS + t;
            int stride = NGEMM_BLOCKS * GEMM_THREADS;
            float4* p = (float4*)out;
            const int n4 = NN * DD / 4;
            for (int j = i; j < n4; j += stride)
                p[j] = make_float4(0.f, 0.f, 0.f, 0.f);
        }

        __half* A16  = (__half*)sm;            // [128][64] = 16KB
        __half* W16s = (__half*)sm + BM * DD;  // [64][128] = 16KB

        int row0 = blockIdx.x * BM;
        // A tile: fp32 -> fp16, coalesced float4 loads, zero-pad past NN
        for (int i = t; i < BM * DD / 4; i += GEMM_THREADS) {
            int m = i >> 4;
            float4 v = make_float4(0.f, 0.f, 0.f, 0.f);
            if (row0 + m < NN)
                v = ((const float4*)(hidden + (size_t)(row0 + m) * DD))[i & 15];
            __half2 h0 = __floats2half2_rn(v.x, v.y);
            __half2 h1 = __floats2half2_rn(v.z, v.w);
            ((__half2*)A16)[i * 2]     = h0;
            ((__half2*)A16)[i * 2 + 1] = h1;
        }
        // W16s[k][a] = a<64 ? Ws[a][k] : Wh[a-64][k]   (L2-hot transpose read)
        for (int i = t; i < DD * 2 * DD; i += GEMM_THREADS) {
            int k = i >> 7, a = i & 127;
            float w = (a < DD) ? Ws[a * DD + k] : Wh[(a - DD) * DD + k];
            W16s[k * 2 * DD + a] = __float2half(w);
        }
        __syncthreads();

        int w = t >> 5, lane = t & 31;
        wmma::fragment<wmma::accumulator, 16, 16, 16, float> c[8];
#pragma unroll
        for (int j = 0; j < 8; j++) wmma::fill_fragment(c[j], 0.f);

#pragma unroll
        for (int kk = 0; kk < 4; kk++) {
            wmma::fragment<wmma::matrix_a, 16, 16, 16, __half, wmma::row_major> a;
            wmma::load_matrix_sync(a, A16 + (w * 16) * DD + kk * 16, DD);
#pragma unroll
            for (int j = 0; j < 8; j++) {
                wmma::fragment<wmma::matrix_b, 16, 16, 16, __half, wmma::row_major> b;
                wmma::load_matrix_sync(b, W16s + kk * 16 * 128 + j * 16, 128);
                wmma::mma_sync(c[j], a, b, c[j]);
            }
        }
        __syncthreads();  // all fragments in registers; safe to reuse smem

        // epilogue: per-warp smem [16][128] fp32 -> interleaved fp16 g_h16
        float* csm = sm + w * 16 * 128;
#pragma unroll
        for (int j = 0; j < 8; j++)
            wmma::store_matrix_sync(csm + j * 16, c[j], 128, wmma::mem_row_major);
        __syncwarp();

        int l16 = lane & 15, rh = lane >> 4;
        int wrow0 = row0 + w * 16;
#pragma unroll
        for (int it = 0; it < 8; it++) {
            int r = it * 2 + rh;
            if (wrow0 + r >= NN) break;
            const float* rp = csm + r * 128;
            float4 hs = *(const float4*)(rp + 4 * l16);        // hsp cols
            float4 hp = *(const float4*)(rp + 64 + 4 * l16);   // hp2 cols
            uint4 hbits;
            ((__half2*)&hbits)[0] = __floats2half2_rn(hs.x, hs.y);
            ((__half2*)&hbits)[1] = __floats2half2_rn(hs.z, hs.w);
            ((__half2*)&hbits)[2] = __floats2half2_rn(hp.x, hp.y);
            ((__half2*)&hbits)[3] = __floats2half2_rn(hp.z, hp.w);
            *(uint4*)(g_h16 + (size_t)(wrow0 + r) * 128 + l16 * 8) = hbits;
        }
        return;
    }

    // ---- relation projection path: 4 rows/block, 64 threads per row ----
    float* WrS  = sm;               // [64][65]
    float* WhS  = sm + DD * 65;     // [64][65]
    float* WqrS = sm + 2 * DD * 65; // [64][65]
    float* rows = sm + 3 * DD * 65; // [4][64]
    for (int i = t; i < DD * DD; i += GEMM_THREADS) {
        int r = i >> 6, c = i & 63;
        WrS [r * 65 + c] = Wr[i];
        WhS [r * 65 + c] = Wh[i];
        WqrS[r * 65 + c] = Wqr[i];
    }
    int sub = t >> 6, a = t & 63;
    int rid = (blockIdx.x - NGEMM_BLOCKS) * 4 + sub;
    bool valid = rid < NPROJ_ROWS;
    int seg = valid ? ((rid >= 2 * NRELTAB) ? 2 : (rid >= NRELTAB) ? 1 : 0) : 0;
    int r = rid - (seg == 2 ? 2 * NRELTAB : seg == 1 ? NRELTAB : 0);
    int src = valid ? (seg == 2 ? qrel[r] : r) : 0;
    rows[sub * DD + a] = emb[src * DD + a];
    __syncthreads();
    if (!valid) return;

    const float* W = (seg == 2) ? WqrS : (seg == 1) ? WhS : WrS;
    const float* rw = rows + sub * DD;
    float acc = (seg == 2) ? bias[a] : 0.f;
#pragma unroll
    for (int k = 0; k < DD; k++) acc = fmaf(rw[k], W[a * 65 + k], acc);

    __half h = __float2half(acc);
    if (seg == 2) {
        g_tqr16[r * DD + a] = h;
    } else {
        int pos = r * 2 * DD + 8 * (a >> 2) + (a & 3) + (seg == 1 ? 4 : 0);
        g_trrp[pos] = h;
    }
}

// ---------------------------------------------------------------------------
// Edge kernel: 16 lanes/edge, 4 consecutive edges per group (hoists wv/wb,
// contiguous 96B index reads). grid 15625 x 256 — residency stays
// scheduler-managed (avoids the R6 fixed-residency occupancy collapse).
// ---------------------------------------------------------------------------
__global__ __launch_bounds__(256)
void edge_kernel(const int* __restrict__ edges,
                 const float* __restrict__ walpha_w,
                 const float* __restrict__ walpha_b,
                 float* __restrict__ out) {
    unsigned gtid = blockIdx.x * blockDim.x + threadIdx.x;
    unsigned g = gtid >> 4;        // group id; 4 edges per group (exact)
    int l = gtid & 15;

    const float4 wv = __ldg((const float4*)walpha_w + l);
    const float wb = __ldg(walpha_b);
    unsigned eid0 = g * EDGE_ITERS;

#pragma unroll
    for (int it = 0; it < EDGE_ITERS; it++) {
        unsigned eid = eid0 + it;
        const int* e = edges + (size_t)eid * 6;
        int v = 0;
        if (l < 4) v = __ldg(e + ((0x5420u >> (l * 4)) & 0xF));  // cols 0,2,4,5
        int r_idx = __shfl_sync(0xffffffffu, v, 0, 16);
        int rel   = __shfl_sync(0xffffffffu, v, 1, 16);
        int sub   = __shfl_sync(0xffffffffu, v, 2, 16);
        int obj   = __shfl_sync(0xffffffffu, v, 3, 16);

        uint4 h  = __ldg((const uint4*)(g_h16 + (size_t)sub * 2 * DD) + l);
        uint4 tt = __ldg((const uint4*)(g_trrp + rel * 2 * DD) + l);
        uint2 tq = __ldg((const uint2*)(g_tqr16 + r_idx * DD) + l);

        float2 a0 = __half22float2(*(const __half2*)&h.x);   // hsp
        float2 a1 = __half22float2(*(const __half2*)&h.y);
        float2 b0 = __half22float2(*(const __half2*)&h.z);   // hp2
        float2 b1 = __half22float2(*(const __half2*)&h.w);
        float2 t0 = __half22float2(*(const __half2*)&tt.x);  // tr
        float2 t1 = __half22float2(*(const __half2*)&tt.y);
        float2 r0 = __half22float2(*(const __half2*)&tt.z);  // rp2
        float2 r1 = __half22float2(*(const __half2*)&tt.w);
        float2 q0 = __half22float2(*(const __half2*)&tq.x);
        float2 q1 = __half22float2(*(const __half2*)&tq.y);

        float p0 = fmaxf(a0.x + t0.x + q0.x, 0.f);
        float p1 = fmaxf(a0.y + t0.y + q0.y, 0.f);
        float p2 = fmaxf(a1.x + t1.x + q1.x, 0.f);
        float p3 = fmaxf(a1.y + t1.y + q1.y, 0.f);
        float part = fmaf(p0, wv.x, fmaf(p1, wv.y, fmaf(p2, wv.z, p3 * wv.w)));
#pragma unroll
        for (int o = 8; o > 0; o >>= 1)
            part += __shfl_xor_sync(0xffffffffu, part, o);

        float alpha = 1.f / (1.f + __expf(-(part + wb)));

        float m0 = alpha * (b0.x + r0.x);
        float m1 = alpha * (b0.y + r0.y);
        float m2 = alpha * (b1.x + r1.x);
        float m3 = alpha * (b1.y + r1.y);

        float* dst = out + (size_t)obj * DD + l * 4;
        asm volatile("red.global.add.v4.f32 [%0], {%1, %2, %3, %4};"
                     :: "l"(dst), "f"(m0), "f"(m1), "f"(m2), "f"(m3)
                     : "memory");
    }
}

// ---------------------------------------------------------------------------
// Inputs (metadata order):
//  0 q_sub[8] i32, 1 q_rel[8] i32, 2 hidden[100000,64] f32, 3 edges[1000000,6] i32,
//  4 nodes[100000,2] i32, 5 old_nodes_new_idx[50000] i32, 6 batchsize i32,
//  7 rel_emb[401,64] f32, 8 Ws[64,64], 9 Wr[64,64], 10 Wqr_w[64,64], 11 Wqr_b[64],
// 12 walpha_w[1,64], 13 walpha_b[1], 14 Wh[64,64]
// Output: hidden_new[100000,64] f32
// ---------------------------------------------------------------------------
extern "C" void kernel_launch(void* const* d_in, const int* in_sizes, int n_in,
                              void* d_out, int out_size) {
    const int*   q_rel    = (const int*)d_in[1];
    const float* hidden   = (const float*)d_in[2];
    const int*   edges    = (const int*)d_in[3];
    const float* rel_emb  = (const float*)d_in[7];
    const float* Ws       = (const float*)d_in[8];
    const float* Wr       = (const float*)d_in[9];
    const float* Wqr_w    = (const float*)d_in[10];
    const float* Wqr_b    = (const float*)d_in[11];
    const float* walpha_w = (const float*)d_in[12];
    const float* walpha_b = (const float*)d_in[13];
    const float* Wh       = (const float*)d_in[14];
    float* out = (float*)d_out;

    cudaFuncSetAttribute(fused_pre_kernel,
                         cudaFuncAttributeMaxDynamicSharedMemorySize, PRE_SMEM);

    fused_pre_kernel<<<NGEMM_BLOCKS + NPROJ_BLOCKS, GEMM_THREADS, PRE_SMEM>>>(
        hidden, Ws, Wh, rel_emb, Wr, Wqr_w, Wqr_b, q_rel, out);
    edge_kernel<<<EDGE_BLOCKS, 256>>>(edges, walpha_w, walpha_b, out);
}

// round 10
// speedup vs baseline: 1.1530x; 1.1530x over previous
#include <cuda_runtime.h>
#include <cuda_fp16.h>
#include <mma.h>

using namespace nvcuda;

#define NN 100000
#define NE 1000000
#define DD 64
#define NRELTAB 401
#define BB 8

#define BM 128
#define GEMM_THREADS 256
#define NGEMM_BLOCKS ((NN + BM - 1) / BM)        // 782 (last block row-guarded)
#define NPROJ_ROWS (2 * NRELTAB + BB)            // 810
#define NPROJ_BLOCKS ((NPROJ_ROWS + 3) / 4)      // 203
// smem: max(A16 4096f + W16s 4096f + stage 2*64*65f = 16642f, epilogue 16384f)
#define PRE_SMEM (16642 * 4 + 256)

#define EDGE_ITERS 4
#define EDGE_BLOCKS (NE / (16 * EDGE_ITERS))     // 15625

// Scratch (static device globals — no runtime allocation).
// g_h16: per node, 128 halves: for l in 0..15: hsp[4l..4l+3] then hp2[4l..4l+3]
//   (hsp = hidden@Ws^T, hp2 = hidden@Wh^T) -> one LDG.128 per lane in edge kernel
__device__ __align__(256) __half g_h16[NN * 2 * DD];
// g_trrp: per relation, 128 halves: for l: tr[4l..4l+3], rp2[4l..4l+3]
__device__ __align__(256) __half g_trrp[NRELTAB * 2 * DD];
__device__ __align__(256) __half g_tqr16[BB * DD];   // rel_emb[q_rel]@Wqr^T + bias

// ---------------------------------------------------------------------------
// Single fused pre-kernel.
//  blocks [0, NGEMM_BLOCKS): zero d_out slice; hidden fp32 tile -> fp16 smem A;
//    W staged COALESCED into padded fp32 smem, then transposed via
//    conflict-free smem reads into fp16 W16s [64][128] (cols Ws^T | Wh^T);
//    wmma 16x16x16 f16->f32 from smem; epilogue -> interleaved fp16 g_h16.
//  blocks [NGEMM_BLOCKS, +NPROJ_BLOCKS): fp32 relation projections (4 rows/blk).
// ---------------------------------------------------------------------------
__global__ __launch_bounds__(GEMM_THREADS)
void fused_pre_kernel(const float* __restrict__ hidden,
                      const float* __restrict__ Ws,
                      const float* __restrict__ Wh,
                      const float* __restrict__ emb,
                      const float* __restrict__ Wr,
                      const float* __restrict__ Wqr,
                      const float* __restrict__ bias,
                      const int* __restrict__ qrel,
                      float* __restrict__ out) {
    extern __shared__ float sm[];
    int t = threadIdx.x;

    if (blockIdx.x < NGEMM_BLOCKS) {
        // zero the output buffer (edge kernel REDs into it)
        {
            int i = blockIdx.x * GEMM_THREADS + t;
            int stride = NGEMM_BLOCKS * GEMM_THREADS;
            float4* p = (float4*)out;
            const int n4 = NN * DD / 4;
            for (int j = i; j < n4; j += stride)
                p[j] = make_float4(0.f, 0.f, 0.f, 0.f);
        }

        __half* A16   = (__half*)sm;                 // [128][64]  = 4096 f
        __half* W16s  = (__half*)sm + BM * DD;       // [64][128]  = 4096 f
        float*  WsStg = sm + 2 * 4096 / 2 * 1 + 4096;          // see offsets below
        // explicit float offsets: A16 occupies floats [0,4096), W16s [4096,8192)
        WsStg = sm + 8192;                           // [64][65]
        float*  WhStg = sm + 8192 + DD * 65;         // [64][65]

        int row0 = blockIdx.x * BM;
        // A tile: fp32 -> fp16, coalesced float4 loads, zero-pad past NN
        for (int i = t; i < BM * DD / 4; i += GEMM_THREADS) {
            int m = i >> 4;
            float4 v = make_float4(0.f, 0.f, 0.f, 0.f);
            if (row0 + m < NN)
                v = ((const float4*)(hidden + (size_t)(row0 + m) * DD))[i & 15];
            ((__half2*)A16)[i * 2]     = __floats2half2_rn(v.x, v.y);
            ((__half2*)A16)[i * 2 + 1] = __floats2half2_rn(v.z, v.w);
        }
        // Stage W coalesced (row-major read; padded smem write, conflict-free)
        for (int i = t; i < DD * DD; i += GEMM_THREADS) {
            int r = i >> 6, c = i & 63;
            WsStg[r * 65 + c] = Ws[i];
            WhStg[r * 65 + c] = Wh[i];
        }
        __syncthreads();
        // Transpose from smem: W16s[k][a] = stage[a][k]; lanes vary a ->
        // bank stride 65 == 1 (mod 32) -> conflict-free reads, coalesced writes
        for (int i = t; i < DD * 2 * DD; i += GEMM_THREADS) {
            int k = i >> 7, a = i & 127;
            float w = (a < DD) ? WsStg[a * 65 + k] : WhStg[(a - DD) * 65 + k];
            W16s[k * 2 * DD + a] = __float2half(w);
        }
        __syncthreads();

        int w = t >> 5, lane = t & 31;
        wmma::fragment<wmma::accumulator, 16, 16, 16, float> c[8];
#pragma unroll
        for (int j = 0; j < 8; j++) wmma::fill_fragment(c[j], 0.f);

#pragma unroll
        for (int kk = 0; kk < 4; kk++) {
            wmma::fragment<wmma::matrix_a, 16, 16, 16, __half, wmma::row_major> a;
            wmma::load_matrix_sync(a, A16 + (w * 16) * DD + kk * 16, DD);
#pragma unroll
            for (int j = 0; j < 8; j++) {
                wmma::fragment<wmma::matrix_b, 16, 16, 16, __half, wmma::row_major> b;
                wmma::load_matrix_sync(b, W16s + kk * 16 * 128 + j * 16, 128);
                wmma::mma_sync(c[j], a, b, c[j]);
            }
        }
        __syncthreads();  // fragments in registers; smem safe to reuse

        // epilogue: per-warp smem [16][128] fp32 -> interleaved fp16 g_h16
        float* csm = sm + w * 16 * 128;
#pragma unroll
        for (int j = 0; j < 8; j++)
            wmma::store_matrix_sync(csm + j * 16, c[j], 128, wmma::mem_row_major);
        __syncwarp();

        int l16 = lane & 15, rh = lane >> 4;
        int wrow0 = row0 + w * 16;
#pragma unroll
        for (int it = 0; it < 8; it++) {
            int r = it * 2 + rh;
            if (wrow0 + r >= NN) break;
            const float* rp = csm + r * 128;
            float4 hs = *(const float4*)(rp + 4 * l16);        // hsp cols
            float4 hp = *(const float4*)(rp + 64 + 4 * l16);   // hp2 cols
            uint4 hbits;
            ((__half2*)&hbits)[0] = __floats2half2_rn(hs.x, hs.y);
            ((__half2*)&hbits)[1] = __floats2half2_rn(hs.z, hs.w);
            ((__half2*)&hbits)[2] = __floats2half2_rn(hp.x, hp.y);
            ((__half2*)&hbits)[3] = __floats2half2_rn(hp.z, hp.w);
            *(uint4*)(g_h16 + (size_t)(wrow0 + r) * 128 + l16 * 8) = hbits;
        }
        return;
    }

    // ---- relation projection path: 4 rows/block, 64 threads per row ----
    float* WrS  = sm;               // [64][65]
    float* WhS  = sm + DD * 65;     // [64][65]
    float* WqrS = sm + 2 * DD * 65; // [64][65]
    float* rows = sm + 3 * DD * 65; // [4][64]
    for (int i = t; i < DD * DD; i += GEMM_THREADS) {
        int r = i >> 6, c = i & 63;
        WrS [r * 65 + c] = Wr[i];
        WhS [r * 65 + c] = Wh[i];
        WqrS[r * 65 + c] = Wqr[i];
    }
    int sub = t >> 6, a = t & 63;
    int rid = (blockIdx.x - NGEMM_BLOCKS) * 4 + sub;
    bool valid = rid < NPROJ_ROWS;
    int seg = valid ? ((rid >= 2 * NRELTAB) ? 2 : (rid >= NRELTAB) ? 1 : 0) : 0;
    int r = rid - (seg == 2 ? 2 * NRELTAB : seg == 1 ? NRELTAB : 0);
    int src = valid ? (seg == 2 ? qrel[r] : r) : 0;
    rows[sub * DD + a] = emb[src * DD + a];
    __syncthreads();
    if (!valid) return;

    const float* W = (seg == 2) ? WqrS : (seg == 1) ? WhS : WrS;
    const float* rw = rows + sub * DD;
    float acc = (seg == 2) ? bias[a] : 0.f;
#pragma unroll
    for (int k = 0; k < DD; k++) acc = fmaf(rw[k], W[a * 65 + k], acc);

    __half h = __float2half(acc);
    if (seg == 2) {
        g_tqr16[r * DD + a] = h;
    } else {
        int pos = r * 2 * DD + 8 * (a >> 2) + (a & 3) + (seg == 1 ? 4 : 0);
        g_trrp[pos] = h;
    }
}

// ---------------------------------------------------------------------------
// Edge kernel (unchanged from R9: 66.3us measured). 16 lanes/edge, 4 edges
// per group, hoisted wv/wb, red.global.add.v4.f32 into d_out.
// ---------------------------------------------------------------------------
__global__ __launch_bounds__(256)
void edge_kernel(const int* __restrict__ edges,
                 const float* __restrict__ walpha_w,
                 const float* __restrict__ walpha_b,
                 float* __restrict__ out) {
    unsigned gtid = blockIdx.x * blockDim.x + threadIdx.x;
    unsigned g = gtid >> 4;
    int l = gtid & 15;

    const float4 wv = __ldg((const float4*)walpha_w + l);
    const float wb = __ldg(walpha_b);
    unsigned eid0 = g * EDGE_ITERS;

#pragma unroll
    for (int it = 0; it < EDGE_ITERS; it++) {
        unsigned eid = eid0 + it;
        const int* e = edges + (size_t)eid * 6;
        int v = 0;
        if (l < 4) v = __ldg(e + ((0x5420u >> (l * 4)) & 0xF));  // cols 0,2,4,5
        int r_idx = __shfl_sync(0xffffffffu, v, 0, 16);
        int rel   = __shfl_sync(0xffffffffu, v, 1, 16);
        int sub   = __shfl_sync(0xffffffffu, v, 2, 16);
        int obj   = __shfl_sync(0xffffffffu, v, 3, 16);

        uint4 h  = __ldg((const uint4*)(g_h16 + (size_t)sub * 2 * DD) + l);
        uint4 tt = __ldg((const uint4*)(g_trrp + rel * 2 * DD) + l);
        uint2 tq = __ldg((const uint2*)(g_tqr16 + r_idx * DD) + l);

        float2 a0 = __half22float2(*(const __half2*)&h.x);
        float2 a1 = __half22float2(*(const __half2*)&h.y);
        float2 b0 = __half22float2(*(const __half2*)&h.z);
        float2 b1 = __half22float2(*(const __half2*)&h.w);
        float2 t0 = __half22float2(*(const __half2*)&tt.x);
        float2 t1 = __half22float2(*(const __half2*)&tt.y);
        float2 r0 = __half22float2(*(const __half2*)&tt.z);
        float2 r1 = __half22float2(*(const __half2*)&tt.w);
        float2 q0 = __half22float2(*(const __half2*)&tq.x);
        float2 q1 = __half22float2(*(const __half2*)&tq.y);

        float p0 = fmaxf(a0.x + t0.x + q0.x, 0.f);
        float p1 = fmaxf(a0.y + t0.y + q0.y, 0.f);
        float p2 = fmaxf(a1.x + t1.x + q1.x, 0.f);
        float p3 = fmaxf(a1.y + t1.y + q1.y, 0.f);
        float part = fmaf(p0, wv.x, fmaf(p1, wv.y, fmaf(p2, wv.z, p3 * wv.w)));
#pragma unroll
        for (int o = 8; o > 0; o >>= 1)
            part += __shfl_xor_sync(0xffffffffu, part, o);

        float alpha = 1.f / (1.f + __expf(-(part + wb)));

        float m0 = alpha * (b0.x + r0.x);
        float m1 = alpha * (b0.y + r0.y);
        float m2 = alpha * (b1.x + r1.x);
        float m3 = alpha * (b1.y + r1.y);

        float* dst = out + (size_t)obj * DD + l * 4;
        asm volatile("red.global.add.v4.f32 [%0], {%1, %2, %3, %4};"
                     :: "l"(dst), "f"(m0), "f"(m1), "f"(m2), "f"(m3)
                     : "memory");
    }
}

// ---------------------------------------------------------------------------
// Inputs (metadata order):
//  0 q_sub[8] i32, 1 q_rel[8] i32, 2 hidden[100000,64] f32, 3 edges[1000000,6] i32,
//  4 nodes[100000,2] i32, 5 old_nodes_new_idx[50000] i32, 6 batchsize i32,
//  7 rel_emb[401,64] f32, 8 Ws[64,64], 9 Wr[64,64], 10 Wqr_w[64,64], 11 Wqr_b[64],
// 12 walpha_w[1,64], 13 walpha_b[1], 14 Wh[64,64]
// Output: hidden_new[100000,64] f32
// ---------------------------------------------------------------------------
extern "C" void kernel_launch(void* const* d_in, const int* in_sizes, int n_in,
                              void* d_out, int out_size) {
    const int*   q_rel    = (const int*)d_in[1];
    const float* hidden   = (const float*)d_in[2];
    const int*   edges    = (const int*)d_in[3];
    const float* rel_emb  = (const float*)d_in[7];
    const float* Ws       = (const float*)d_in[8];
    const float* Wr       = (const float*)d_in[9];
    const float* Wqr_w    = (const float*)d_in[10];
    const float* Wqr_b    = (const float*)d_in[11];
    const float* walpha_w = (const float*)d_in[12];
    const float* walpha_b = (const float*)d_in[13];
    const float* Wh       = (const float*)d_in[14];
    float* out = (float*)d_out;

    cudaFuncSetAttribute(fused_pre_kernel,
                         cudaFuncAttributeMaxDynamicSharedMemorySize, PRE_SMEM);

    fused_pre_kernel<<<NGEMM_BLOCKS + NPROJ_BLOCKS, GEMM_THREADS, PRE_SMEM>>>(
        hidden, Ws, Wh, rel_emb, Wr, Wqr_w, Wqr_b, q_rel, out);
    edge_kernel<<<EDGE_BLOCKS, 256>>>(edges, walpha_w, walpha_b, out);
}